// round 1
// baseline (speedup 1.0000x reference)
#include <cuda_runtime.h>
#include <cuda_bf16.h>

// Problem constants
#define Bv   32
#define Nv   128
#define Fv   78
#define Hv   256
#define Sv   20
#define Tv   13
#define Lv   3
#define ALPHA 0.2f
#define NEG_INF -9000000000000000.0f

#define BN (Bv*Nv)          // 4096 rows

// Scratch (device globals; no allocation allowed)
__device__ float g_x[BN*Hv];      // activations (ping)
__device__ float g_h[BN*Hv];      // per-layer projected h (pong)
__device__ float g_s1[BN];
__device__ float g_s2[BN];
__device__ float g_graph[Bv*Hv];

// ---------------------------------------------------------------------------
// K1: x = node_features @ W_node + b_node    (4096 x 78) @ (78 x 256)
// one block per row, 256 threads, x-row staged in smem
// ---------------------------------------------------------------------------
__global__ void k_node_proj(const float* __restrict__ nf,
                            const float* __restrict__ W,
                            const float* __restrict__ bias)
{
    int row = blockIdx.x;            // b*N + n
    int j   = threadIdx.x;           // 0..255
    __shared__ float sf[Fv];
    if (j < Fv) sf[j] = nf[row*Fv + j];
    __syncthreads();
    float acc = bias[j];
#pragma unroll
    for (int f = 0; f < Fv; ++f)
        acc += sf[f] * W[f*Hv + j];
    g_x[row*Hv + j] = acc;
}

// ---------------------------------------------------------------------------
// K2: h = x @ gat_W[l]  (+ per-row scores s1 = h.a1, s2 = h.a2)
// 8 rows per block, 256 threads (thread = output column), register tiling.
// ---------------------------------------------------------------------------
#define PROJ_ROWS 8
__global__ void k_gat_proj(const float* __restrict__ W,   // [256,256] row-major
                           const float* __restrict__ a)   // [512] (a1 | a2)
{
    int row0 = blockIdx.x * PROJ_ROWS;
    int j    = threadIdx.x;
    int lane = j & 31, warp = j >> 5;

    __shared__ __align__(16) float sx[Hv][PROJ_ROWS];   // [k][r] for float4 loads
#pragma unroll
    for (int r = 0; r < PROJ_ROWS; ++r)
        sx[j][r] = g_x[(row0 + r)*Hv + j];
    __syncthreads();

    float acc[PROJ_ROWS];
#pragma unroll
    for (int r = 0; r < PROJ_ROWS; ++r) acc[r] = 0.f;

#pragma unroll 4
    for (int k = 0; k < Hv; ++k) {
        float w = W[k*Hv + j];
        float4 xa = *reinterpret_cast<const float4*>(&sx[k][0]);
        float4 xb = *reinterpret_cast<const float4*>(&sx[k][4]);
        acc[0] += xa.x * w;  acc[1] += xa.y * w;
        acc[2] += xa.z * w;  acc[3] += xa.w * w;
        acc[4] += xb.x * w;  acc[5] += xb.y * w;
        acc[6] += xb.z * w;  acc[7] += xb.w * w;
    }

#pragma unroll
    for (int r = 0; r < PROJ_ROWS; ++r)
        g_h[(row0 + r)*Hv + j] = acc[r];

    // score reductions: s1[r] = sum_j acc[r]*a1[j], s2[r] = sum_j acc[r]*a2[j]
    float a1j = a[j], a2j = a[Hv + j];
    __shared__ float red1[8][PROJ_ROWS], red2[8][PROJ_ROWS];
#pragma unroll
    for (int r = 0; r < PROJ_ROWS; ++r) {
        float v1 = acc[r] * a1j;
        float v2 = acc[r] * a2j;
#pragma unroll
        for (int off = 16; off > 0; off >>= 1) {
            v1 += __shfl_xor_sync(0xffffffffu, v1, off);
            v2 += __shfl_xor_sync(0xffffffffu, v2, off);
        }
        if (lane == 0) { red1[warp][r] = v1; red2[warp][r] = v2; }
    }
    __syncthreads();
    if (j < 2*PROJ_ROWS) {
        int r = j & (PROJ_ROWS-1);
        bool second = j >= PROJ_ROWS;
        float s = 0.f;
#pragma unroll
        for (int w = 0; w < 8; ++w)
            s += second ? red2[w][r] : red1[w][r];
        if (second) g_s2[row0 + r] = s;
        else        g_s1[row0 + r] = s;
    }
}

// ---------------------------------------------------------------------------
// K3: attention softmax + aggregation + relu  -> writes g_x
// grid (16, 32): block handles 8 target rows i of batch b; 256 threads.
// Warp w computes softmax for row i0+w (128 j's, 4 per lane).
// Then thread t owns channel t: acc[r] += att[r][j] * h[b,j,t] over j.
// ---------------------------------------------------------------------------
#define AGG_ROWS 8
__global__ void k_gat_agg(const int* __restrict__ adj)
{
    int b  = blockIdx.y;
    int i0 = blockIdx.x * AGG_ROWS;
    int t  = threadIdx.x;
    int lane = t & 31, warp = t >> 5;

    __shared__ float s2_sh[Nv];
    __shared__ __align__(16) float att[Nv][AGG_ROWS];   // [j][i]

    if (t < Nv) s2_sh[t] = g_s2[b*Nv + t];
    __syncthreads();

    // softmax for row i = i0 + warp
    {
        int i = i0 + warp;
        float s1i = g_s1[b*Nv + i];
        const int* adj_row = adj + (size_t)(b*Nv + i)*Nv;
        float e[4];
        float mx = NEG_INF;
#pragma unroll
        for (int q = 0; q < 4; ++q) {
            int jj = lane + q*32;
            float v = s1i + s2_sh[jj];
            v = (v > 0.f) ? v : ALPHA * v;          // leaky_relu
            v = (adj_row[jj] > 0) ? v : NEG_INF;    // mask
            e[q] = v;
            mx = fmaxf(mx, v);
        }
#pragma unroll
        for (int off = 16; off > 0; off >>= 1)
            mx = fmaxf(mx, __shfl_xor_sync(0xffffffffu, mx, off));
        float sum = 0.f;
#pragma unroll
        for (int q = 0; q < 4; ++q) {
            e[q] = __expf(e[q] - mx);
            sum += e[q];
        }
#pragma unroll
        for (int off = 16; off > 0; off >>= 1)
            sum += __shfl_xor_sync(0xffffffffu, sum, off);
        float inv = 1.f / sum;
#pragma unroll
        for (int q = 0; q < 4; ++q)
            att[lane + q*32][warp] = e[q] * inv;
    }
    __syncthreads();

    // aggregation: channel t, 8 row accumulators
    const float* hb = g_h + (size_t)b*Nv*Hv;
    float acc[AGG_ROWS];
#pragma unroll
    for (int r = 0; r < AGG_ROWS; ++r) acc[r] = 0.f;

#pragma unroll 4
    for (int j = 0; j < Nv; ++j) {
        float hv = hb[j*Hv + t];
        float4 w0 = *reinterpret_cast<const float4*>(&att[j][0]);
        float4 w1 = *reinterpret_cast<const float4*>(&att[j][4]);
        acc[0] += w0.x * hv;  acc[1] += w0.y * hv;
        acc[2] += w0.z * hv;  acc[3] += w0.w * hv;
        acc[4] += w1.x * hv;  acc[5] += w1.y * hv;
        acc[6] += w1.z * hv;  acc[7] += w1.w * hv;
    }
#pragma unroll
    for (int r = 0; r < AGG_ROWS; ++r)
        g_x[(size_t)(b*Nv + i0 + r)*Hv + t] = fmaxf(acc[r], 0.f);
}

// ---------------------------------------------------------------------------
// K4: graph mean over nodes
// ---------------------------------------------------------------------------
__global__ void k_mean()
{
    int b = blockIdx.x, t = threadIdx.x;
    float s = 0.f;
#pragma unroll 4
    for (int n = 0; n < Nv; ++n)
        s += g_x[(size_t)(b*Nv + n)*Hv + t];
    g_graph[b*Hv + t] = s * (1.0f/Nv);
}

// ---------------------------------------------------------------------------
// K5: fused head. One block per batch element.
// ---------------------------------------------------------------------------
__global__ void k_head(const float* __restrict__ scaffold,  // [B,20]
                       const float* __restrict__ W_sc,      // [20,256]
                       const float* __restrict__ b_sc,      // [256]
                       const float* __restrict__ gp_w1,     // [256,128]
                       const float* __restrict__ gp_b1,     // [128]
                       const float* __restrict__ gp_w2,     // [128,64]
                       const float* __restrict__ gp_b2,     // [64]
                       const float* __restrict__ out_w1,    // [128,128]
                       const float* __restrict__ out_b1,    // [128]
                       const float* __restrict__ out_w2,    // [128,13]
                       const float* __restrict__ out_b2,    // [13]
                       float* __restrict__ out)             // [B,13]
{
    int b = blockIdx.x, t = threadIdx.x;
    __shared__ float scaf[Sv];
    __shared__ float grow[Hv];
    __shared__ float sc[Hv];
    __shared__ float g1[128], sp1[128];
    __shared__ float c[128];        // [g2 | sp2]
    __shared__ float hdn[128];

    if (t < Sv) scaf[t] = scaffold[b*Sv + t];
    grow[t] = g_graph[b*Hv + t];
    __syncthreads();

    // sc = scaffold @ W_sc + b_sc   (256 outputs, K=20)
    {
        float acc = b_sc[t];
#pragma unroll
        for (int k = 0; k < Sv; ++k)
            acc += scaf[k] * W_sc[k*Hv + t];
        sc[t] = acc;
    }
    __syncthreads();

    // layer 1 of pool for both branches (128 outputs each, K=256)
    {
        int col = t & 127;
        const float* src = (t < 128) ? grow : sc;
        float acc = gp_b1[col];
#pragma unroll 4
        for (int k = 0; k < Hv; ++k)
            acc += src[k] * gp_w1[k*128 + col];
        acc = fmaxf(acc, 0.f);
        if (t < 128) g1[col] = acc; else sp1[col] = acc;
    }
    __syncthreads();

    // layer 2 of pool for both branches (64 outputs each, K=128) -> c
    if (t < 128) {
        int col = t & 63;
        const float* src = (t < 64) ? g1 : sp1;
        float acc = gp_b2[col];
#pragma unroll 4
        for (int k = 0; k < 128; ++k)
            acc += src[k] * gp_w2[k*64 + col];
        c[t] = fmaxf(acc, 0.f);   // c[0..63]=g2, c[64..127]=sp2
    }
    __syncthreads();

    // hdn = relu(c @ out_w1 + out_b1)   (128 outputs, K=128)
    if (t < 128) {
        float acc = out_b1[t];
#pragma unroll 4
        for (int k = 0; k < 128; ++k)
            acc += c[k] * out_w1[k*128 + t];
        hdn[t] = fmaxf(acc, 0.f);
    }
    __syncthreads();

    // out = hdn @ out_w2 + out_b2      (13 outputs, K=128)
    if (t < Tv) {
        float acc = out_b2[t];
#pragma unroll 4
        for (int k = 0; k < 128; ++k)
            acc += hdn[k] * out_w2[k*Tv + t];
        out[b*Tv + t] = acc;
    }
}

// ---------------------------------------------------------------------------
extern "C" void kernel_launch(void* const* d_in, const int* in_sizes, int n_in,
                              void* d_out, int out_size)
{
    const float* node_features     = (const float*)d_in[0];
    // d_in[1] = edge_features — unused by the reference
    const int*   adj_matrix        = (const int*)  d_in[2];
    const float* scaffold_features = (const float*)d_in[3];
    const float* W_node            = (const float*)d_in[4];
    const float* b_node            = (const float*)d_in[5];
    const float* gat_W             = (const float*)d_in[6];
    const float* gat_a             = (const float*)d_in[7];
    const float* W_sc              = (const float*)d_in[8];
    const float* b_sc              = (const float*)d_in[9];
    const float* gp_w1             = (const float*)d_in[10];
    const float* gp_b1             = (const float*)d_in[11];
    const float* gp_w2             = (const float*)d_in[12];
    const float* gp_b2             = (const float*)d_in[13];
    const float* out_w1            = (const float*)d_in[14];
    const float* out_b1            = (const float*)d_in[15];
    const float* out_w2            = (const float*)d_in[16];
    const float* out_b2            = (const float*)d_in[17];
    float* out = (float*)d_out;

    k_node_proj<<<BN, Hv>>>(node_features, W_node, b_node);

    for (int l = 0; l < Lv; ++l) {
        k_gat_proj<<<BN/PROJ_ROWS, Hv>>>(gat_W + (size_t)l*Hv*Hv,
                                         gat_a + (size_t)l*2*Hv);
        dim3 grid(Nv/AGG_ROWS, Bv);
        k_gat_agg<<<grid, Hv>>>(adj_matrix);
    }

    k_mean<<<Bv, Hv>>>();

    k_head<<<Bv, Hv>>>(scaffold_features, W_sc, b_sc,
                       gp_w1, gp_b1, gp_w2, gp_b2,
                       out_w1, out_b1, out_w2, out_b2, out);
}

// round 2
// speedup vs baseline: 1.0690x; 1.0690x over previous
#include <cuda_runtime.h>
#include <cuda_bf16.h>

// Problem constants
#define Bv   32
#define Nv   128
#define Fv   78
#define Hv   256
#define Sv   20
#define Tv   13
#define Lv   3
#define ALPHA 0.2f
#define NEG_INF -9000000000000000.0f

#define BN (Bv*Nv)          // 4096 rows

// Scratch (device globals; no allocation allowed)
__device__ float g_x[BN*Hv];      // activations (ping)
__device__ float g_h[BN*Hv];      // per-layer projected h (pong)
__device__ float g_s1[BN];
__device__ float g_s2[BN];
__device__ float g_graph[Bv*Hv];

// ---------------------------------------------------------------------------
// K1: x = node_features @ W_node + b_node    (4096 x 78) @ (78 x 256)
// 8 rows per block, 256 threads (thread = output column), register tiling.
// ---------------------------------------------------------------------------
#define NP_ROWS 8
__global__ void k_node_proj(const float* __restrict__ nf,
                            const float* __restrict__ W,
                            const float* __restrict__ bias)
{
    int row0 = blockIdx.x * NP_ROWS;
    int j    = threadIdx.x;

    __shared__ __align__(16) float sf[Fv * NP_ROWS];   // [f][r]
    for (int idx = j; idx < Fv*NP_ROWS; idx += 256) {
        int f = idx >> 3, r = idx & 7;
        sf[idx] = nf[(row0 + r)*Fv + f];
    }
    __syncthreads();

    float bj = bias[j];
    float acc[NP_ROWS];
#pragma unroll
    for (int r = 0; r < NP_ROWS; ++r) acc[r] = bj;

#pragma unroll 6
    for (int f = 0; f < Fv; ++f) {
        float w = W[f*Hv + j];
        const float4* xp = reinterpret_cast<const float4*>(&sf[f*NP_ROWS]);
        float4 xa = xp[0], xb = xp[1];
        acc[0] += xa.x * w;  acc[1] += xa.y * w;
        acc[2] += xa.z * w;  acc[3] += xa.w * w;
        acc[4] += xb.x * w;  acc[5] += xb.y * w;
        acc[6] += xb.z * w;  acc[7] += xb.w * w;
    }
#pragma unroll
    for (int r = 0; r < NP_ROWS; ++r)
        g_x[(row0 + r)*Hv + j] = acc[r];
}

// ---------------------------------------------------------------------------
// K2: h = x @ gat_W[l]  (+ per-row scores s1 = h.a1, s2 = h.a2)
// 16 rows per block, 256 threads, W chunks staged in smem.
// ---------------------------------------------------------------------------
#define PROJ_ROWS 16
#define SX_STRIDE 20            // pad: 16B-aligned, reduces STS conflicts
#define KC 16
__global__ void k_gat_proj(const float* __restrict__ W,   // [256,256] row-major
                           const float* __restrict__ a)   // [512] (a1 | a2)
{
    const int row0 = blockIdx.x * PROJ_ROWS;
    const int j    = threadIdx.x;
    const int lane = j & 31, warp = j >> 5;

    __shared__ __align__(16) float sx[Hv * SX_STRIDE];    // [k][r]
    __shared__ __align__(16) float sw[KC * Hv];           // [kk][col]
    __shared__ float red1[8][PROJ_ROWS], red2[8][PROJ_ROWS];

    // stage all 16 x-rows (thread j loads column j)
#pragma unroll
    for (int r = 0; r < PROJ_ROWS; ++r)
        sx[j*SX_STRIDE + r] = g_x[(row0 + r)*Hv + j];

    float acc[PROJ_ROWS];
#pragma unroll
    for (int r = 0; r < PROJ_ROWS; ++r) acc[r] = 0.f;

    for (int kc = 0; kc < Hv; kc += KC) {
        __syncthreads();
        // stage W chunk [KC][256] via float4 (coalesced)
        const float4* Wv  = reinterpret_cast<const float4*>(W + kc*Hv);
        float4*       swv = reinterpret_cast<float4*>(sw);
#pragma unroll
        for (int q = 0; q < 4; ++q)
            swv[q*256 + j] = Wv[q*256 + j];
        __syncthreads();

#pragma unroll
        for (int kk = 0; kk < KC; ++kk) {
            float w = sw[kk*Hv + j];
            const float4* xp =
                reinterpret_cast<const float4*>(&sx[(kc + kk)*SX_STRIDE]);
            float4 x0 = xp[0], x1 = xp[1], x2 = xp[2], x3 = xp[3];
            acc[0]  += x0.x * w;  acc[1]  += x0.y * w;
            acc[2]  += x0.z * w;  acc[3]  += x0.w * w;
            acc[4]  += x1.x * w;  acc[5]  += x1.y * w;
            acc[6]  += x1.z * w;  acc[7]  += x1.w * w;
            acc[8]  += x2.x * w;  acc[9]  += x2.y * w;
            acc[10] += x2.z * w;  acc[11] += x2.w * w;
            acc[12] += x3.x * w;  acc[13] += x3.y * w;
            acc[14] += x3.z * w;  acc[15] += x3.w * w;
        }
    }

#pragma unroll
    for (int r = 0; r < PROJ_ROWS; ++r)
        g_h[(row0 + r)*Hv + j] = acc[r];

    // scores: s1[r] = sum_j acc[r]*a1[j], s2[r] = sum_j acc[r]*a2[j]
    float a1j = a[j], a2j = a[Hv + j];
#pragma unroll
    for (int r = 0; r < PROJ_ROWS; ++r) {
        float v1 = acc[r] * a1j;
        float v2 = acc[r] * a2j;
#pragma unroll
        for (int off = 16; off > 0; off >>= 1) {
            v1 += __shfl_xor_sync(0xffffffffu, v1, off);
            v2 += __shfl_xor_sync(0xffffffffu, v2, off);
        }
        if (lane == 0) { red1[warp][r] = v1; red2[warp][r] = v2; }
    }
    __syncthreads();
    if (j < 2*PROJ_ROWS) {
        int r = j & (PROJ_ROWS-1);
        bool second = j >= PROJ_ROWS;
        float s = 0.f;
#pragma unroll
        for (int w = 0; w < 8; ++w)
            s += second ? red2[w][r] : red1[w][r];
        if (second) g_s2[row0 + r] = s;
        else        g_s1[row0 + r] = s;
    }
}

// ---------------------------------------------------------------------------
// K3: attention softmax + aggregation + relu -> g_x (or mean -> g_graph)
// grid (8, 32): block handles 16 target rows of batch b; 256 threads.
// h chunks staged in smem; att tile [j][16] padded.
// ---------------------------------------------------------------------------
#define AGG_ROWS 16
#define AT_STRIDE 20
__global__ void k_gat_agg(const int* __restrict__ adj, int last)
{
    int b  = blockIdx.y;
    int i0 = blockIdx.x * AGG_ROWS;
    int t  = threadIdx.x;
    int lane = t & 31, warp = t >> 5;

    __shared__ float s2_sh[Nv];
    __shared__ __align__(16) float att[Nv * AT_STRIDE];  // [j][i_local]
    __shared__ __align__(16) float sh[16 * Hv];          // h chunk [jj][ch]

    if (t < Nv) s2_sh[t] = g_s2[b*Nv + t];
    __syncthreads();

    // softmax: warp handles local rows 2*warp, 2*warp+1
#pragma unroll
    for (int rr = 0; rr < 2; ++rr) {
        int il = warp*2 + rr;
        int i  = i0 + il;
        float s1i = g_s1[b*Nv + i];
        const int* adj_row = adj + (size_t)(b*Nv + i)*Nv;
        float e[4];
        float mx = NEG_INF;
#pragma unroll
        for (int q = 0; q < 4; ++q) {
            int jj = lane + q*32;
            float v = s1i + s2_sh[jj];
            v = (v > 0.f) ? v : ALPHA * v;          // leaky_relu
            v = (adj_row[jj] > 0) ? v : NEG_INF;    // mask
            e[q] = v;
            mx = fmaxf(mx, v);
        }
#pragma unroll
        for (int off = 16; off > 0; off >>= 1)
            mx = fmaxf(mx, __shfl_xor_sync(0xffffffffu, mx, off));
        float sum = 0.f;
#pragma unroll
        for (int q = 0; q < 4; ++q) {
            e[q] = __expf(e[q] - mx);
            sum += e[q];
        }
#pragma unroll
        for (int off = 16; off > 0; off >>= 1)
            sum += __shfl_xor_sync(0xffffffffu, sum, off);
        float inv = 1.f / sum;
#pragma unroll
        for (int q = 0; q < 4; ++q)
            att[(lane + q*32)*AT_STRIDE + il] = e[q] * inv;
    }

    float acc[AGG_ROWS];
#pragma unroll
    for (int r = 0; r < AGG_ROWS; ++r) acc[r] = 0.f;

    const float4* hv4 = reinterpret_cast<const float4*>(g_h + (size_t)b*Nv*Hv);
    float4* shv = reinterpret_cast<float4*>(sh);

    for (int jc = 0; jc < Nv; jc += 16) {
        __syncthreads();   // att ready (first iter) / prev chunk consumed
        // stage h[b][jc..jc+15][0..255] (contiguous 16KB, coalesced)
#pragma unroll
        for (int q = 0; q < 4; ++q)
            shv[q*256 + t] = hv4[(size_t)jc*64 + q*256 + t];
        __syncthreads();

#pragma unroll
        for (int kk = 0; kk < 16; ++kk) {
            float hv = sh[kk*Hv + t];
            const float4* wp =
                reinterpret_cast<const float4*>(&att[(jc + kk)*AT_STRIDE]);
            float4 w0 = wp[0], w1 = wp[1], w2 = wp[2], w3 = wp[3];
            acc[0]  += w0.x * hv;  acc[1]  += w0.y * hv;
            acc[2]  += w0.z * hv;  acc[3]  += w0.w * hv;
            acc[4]  += w1.x * hv;  acc[5]  += w1.y * hv;
            acc[6]  += w1.z * hv;  acc[7]  += w1.w * hv;
            acc[8]  += w2.x * hv;  acc[9]  += w2.y * hv;
            acc[10] += w2.z * hv;  acc[11] += w2.w * hv;
            acc[12] += w3.x * hv;  acc[13] += w3.y * hv;
            acc[14] += w3.z * hv;  acc[15] += w3.w * hv;
        }
    }

    if (last) {
        // fused mean partial: sum of this block's 16 relu'd rows, channel t
        float partial = 0.f;
#pragma unroll
        for (int r = 0; r < AGG_ROWS; ++r)
            partial += fmaxf(acc[r], 0.f);
        atomicAdd(&g_graph[b*Hv + t], partial);
    } else {
#pragma unroll
        for (int r = 0; r < AGG_ROWS; ++r)
            g_x[(size_t)(b*Nv + i0 + r)*Hv + t] = fmaxf(acc[r], 0.f);
    }
}

// ---------------------------------------------------------------------------
// K5: fused head. One block per batch element.
// ---------------------------------------------------------------------------
__global__ void k_head(const float* __restrict__ scaffold,  // [B,20]
                       const float* __restrict__ W_sc,      // [20,256]
                       const float* __restrict__ b_sc,      // [256]
                       const float* __restrict__ gp_w1,     // [256,128]
                       const float* __restrict__ gp_b1,     // [128]
                       const float* __restrict__ gp_w2,     // [128,64]
                       const float* __restrict__ gp_b2,     // [64]
                       const float* __restrict__ out_w1,    // [128,128]
                       const float* __restrict__ out_b1,    // [128]
                       const float* __restrict__ out_w2,    // [128,13]
                       const float* __restrict__ out_b2,    // [13]
                       float* __restrict__ out)             // [B,13]
{
    int b = blockIdx.x, t = threadIdx.x;
    __shared__ float scaf[Sv];
    __shared__ float grow[Hv];
    __shared__ float sc[Hv];
    __shared__ float g1[128], sp1[128];
    __shared__ float c[128];        // [g2 | sp2]
    __shared__ float hdn[128];

    if (t < Sv) scaf[t] = scaffold[b*Sv + t];
    grow[t] = g_graph[b*Hv + t] * (1.0f/Nv);   // finish the mean here
    __syncthreads();

    // sc = scaffold @ W_sc + b_sc   (256 outputs, K=20)
    {
        float acc = b_sc[t];
#pragma unroll
        for (int k = 0; k < Sv; ++k)
            acc += scaf[k] * W_sc[k*Hv + t];
        sc[t] = acc;
    }
    __syncthreads();

    // layer 1 of pool for both branches (128 outputs each, K=256)
    {
        int col = t & 127;
        const float* src = (t < 128) ? grow : sc;
        float acc = gp_b1[col];
#pragma unroll 4
        for (int k = 0; k < Hv; ++k)
            acc += src[k] * gp_w1[k*128 + col];
        acc = fmaxf(acc, 0.f);
        if (t < 128) g1[col] = acc; else sp1[col] = acc;
    }
    __syncthreads();

    // layer 2 of pool for both branches (64 outputs each, K=128) -> c
    if (t < 128) {
        int col = t & 63;
        const float* src = (t < 64) ? g1 : sp1;
        float acc = gp_b2[col];
#pragma unroll 4
        for (int k = 0; k < 128; ++k)
            acc += src[k] * gp_w2[k*64 + col];
        c[t] = fmaxf(acc, 0.f);   // c[0..63]=g2, c[64..127]=sp2
    }
    __syncthreads();

    // hdn = relu(c @ out_w1 + out_b1)   (128 outputs, K=128)
    if (t < 128) {
        float acc = out_b1[t];
#pragma unroll 4
        for (int k = 0; k < 128; ++k)
            acc += c[k] * out_w1[k*128 + t];
        hdn[t] = fmaxf(acc, 0.f);
    }
    __syncthreads();

    // out = hdn @ out_w2 + out_b2      (13 outputs, K=128)
    if (t < Tv) {
        float acc = out_b2[t];
#pragma unroll 4
        for (int k = 0; k < 128; ++k)
            acc += hdn[k] * out_w2[k*Tv + t];
        out[b*Tv + t] = acc;
    }
}

// ---------------------------------------------------------------------------
extern "C" void kernel_launch(void* const* d_in, const int* in_sizes, int n_in,
                              void* d_out, int out_size)
{
    const float* node_features     = (const float*)d_in[0];
    // d_in[1] = edge_features — unused by the reference
    const int*   adj_matrix        = (const int*)  d_in[2];
    const float* scaffold_features = (const float*)d_in[3];
    const float* W_node            = (const float*)d_in[4];
    const float* b_node            = (const float*)d_in[5];
    const float* gat_W             = (const float*)d_in[6];
    const float* gat_a             = (const float*)d_in[7];
    const float* W_sc              = (const float*)d_in[8];
    const float* b_sc              = (const float*)d_in[9];
    const float* gp_w1             = (const float*)d_in[10];
    const float* gp_b1             = (const float*)d_in[11];
    const float* gp_w2             = (const float*)d_in[12];
    const float* gp_b2             = (const float*)d_in[13];
    const float* out_w1            = (const float*)d_in[14];
    const float* out_b1            = (const float*)d_in[15];
    const float* out_w2            = (const float*)d_in[16];
    const float* out_b2            = (const float*)d_in[17];
    float* out = (float*)d_out;

    // zero the mean accumulator (used by the fused last-layer agg)
    void* graph_ptr = nullptr;
    cudaGetSymbolAddress(&graph_ptr, g_graph);
    cudaMemsetAsync(graph_ptr, 0, Bv*Hv*sizeof(float));

    k_node_proj<<<BN/NP_ROWS, Hv>>>(node_features, W_node, b_node);

    for (int l = 0; l < Lv; ++l) {
        k_gat_proj<<<BN/PROJ_ROWS, Hv>>>(gat_W + (size_t)l*Hv*Hv,
                                         gat_a + (size_t)l*2*Hv);
        dim3 grid(Nv/AGG_ROWS, Bv);
        k_gat_agg<<<grid, Hv>>>(adj_matrix, l == Lv-1);
    }

    k_head<<<Bv, Hv>>>(scaffold_features, W_sc, b_sc,
                       gp_w1, gp_b1, gp_w2, gp_b2,
                       out_w1, out_b1, out_w2, out_b2, out);
}

// round 3
// speedup vs baseline: 1.2787x; 1.1962x over previous
#include <cuda_runtime.h>
#include <cuda_bf16.h>

// Problem constants
#define Bv   32
#define Nv   128
#define Fv   78
#define Hv   256
#define Sv   20
#define Tv   13
#define Lv   3
#define ALPHA 0.2f
#define NEG_INF -9000000000000000.0f

#define BN (Bv*Nv)          // 4096 rows

// Scratch (device globals; no allocation allowed)
__device__ float g_xT[Hv*BN];                 // activations TRANSPOSED [c][row]
__device__ float g_h[BN*Hv];                  // projected h, normal [row][c]
__device__ float g_zbuf[Lv*2*BN + Bv*Hv];     // s1/s2 per layer (atomic) + graph accum

#define GRAPH_OFF (Lv*2*BN)

// ---------------------------------------------------------------------------
// K1: x = node_features @ W_node + b_node -> g_xT (transposed)
// 8 rows per block, 256 threads (thread = output column)
// ---------------------------------------------------------------------------
#define NP_ROWS 8
__global__ void k_node_proj(const float* __restrict__ nf,
                            const float* __restrict__ W,
                            const float* __restrict__ bias)
{
    int row0 = blockIdx.x * NP_ROWS;
    int j    = threadIdx.x;

    __shared__ __align__(16) float sf[Fv * NP_ROWS];   // [f][r]
    __shared__ float st[NP_ROWS * 257];                // transpose tile

    for (int idx = j; idx < Fv*NP_ROWS; idx += 256) {
        int f = idx >> 3, r = idx & 7;
        sf[idx] = nf[(row0 + r)*Fv + f];
    }
    __syncthreads();

    float bj = bias[j];
    float acc[NP_ROWS];
#pragma unroll
    for (int r = 0; r < NP_ROWS; ++r) acc[r] = bj;

#pragma unroll 6
    for (int f = 0; f < Fv; ++f) {
        float w = W[f*Hv + j];
        const float4* xp = reinterpret_cast<const float4*>(&sf[f*NP_ROWS]);
        float4 xa = xp[0], xb = xp[1];
        acc[0] += xa.x * w;  acc[1] += xa.y * w;
        acc[2] += xa.z * w;  acc[3] += xa.w * w;
        acc[4] += xb.x * w;  acc[5] += xb.y * w;
        acc[6] += xb.z * w;  acc[7] += xb.w * w;
    }

    // transpose through smem, then coalesced-ish STG to g_xT[c][row]
#pragma unroll
    for (int r = 0; r < NP_ROWS; ++r)
        st[r*257 + j] = acc[r];
    __syncthreads();
    int r = j & 7;
    int cb = j >> 3;          // 0..31
#pragma unroll
    for (int p = 0; p < 8; ++p) {
        int c = cb + 32*p;
        g_xT[(size_t)c*BN + row0 + r] = st[r*257 + c];
    }
}

// ---------------------------------------------------------------------------
// K2: h = x @ gat_W[l]  + partial scores via atomics
// Block: 64 rows x 64 cols; 256 threads; thread = 4x4 tile.
// x read from g_xT (transposed), W chunks staged in smem.
// ---------------------------------------------------------------------------
#define KC 64
__global__ void k_gat_proj(const float* __restrict__ W,   // [256,256]
                           const float* __restrict__ a,   // [512]
                           int layer)
{
    const int row0 = blockIdx.x * 64;
    const int c0   = blockIdx.y * 64;
    const int t  = threadIdx.x;
    const int tx = t & 15, ty = t >> 4;

    float* s1 = g_zbuf + layer*2*BN;
    float* s2 = s1 + BN;

    __shared__ __align__(16) float sx[KC * 68];   // [k][row], padded
    __shared__ __align__(16) float sw[KC * 64];   // [k][col]

    float acc[16];
#pragma unroll
    for (int i = 0; i < 16; ++i) acc[i] = 0.f;

    const int ks = t >> 4;   // 0..15
    const int f  = t & 15;   // 0..15 (float4 index)

    for (int kc = 0; kc < Hv; kc += KC) {
        __syncthreads();
#pragma unroll
        for (int m = 0; m < 4; ++m) {
            int k = ks + 16*m;
            float4 xv = *reinterpret_cast<const float4*>(
                            &g_xT[(size_t)(kc + k)*BN + row0 + 4*f]);
            *reinterpret_cast<float4*>(&sx[k*68 + 4*f]) = xv;
            float4 wv = *reinterpret_cast<const float4*>(
                            &W[(kc + k)*Hv + c0 + 4*f]);
            *reinterpret_cast<float4*>(&sw[(k<<6) + 4*f]) = wv;
        }
        __syncthreads();

#pragma unroll 8
        for (int k = 0; k < KC; ++k) {
            float4 xv = *reinterpret_cast<const float4*>(&sx[k*68 + 4*ty]);
            float4 wv = *reinterpret_cast<const float4*>(&sw[(k<<6) + 4*tx]);
            acc[0]  += xv.x*wv.x; acc[1]  += xv.x*wv.y;
            acc[2]  += xv.x*wv.z; acc[3]  += xv.x*wv.w;
            acc[4]  += xv.y*wv.x; acc[5]  += xv.y*wv.y;
            acc[6]  += xv.y*wv.z; acc[7]  += xv.y*wv.w;
            acc[8]  += xv.z*wv.x; acc[9]  += xv.z*wv.y;
            acc[10] += xv.z*wv.z; acc[11] += xv.z*wv.w;
            acc[12] += xv.w*wv.x; acc[13] += xv.w*wv.y;
            acc[14] += xv.w*wv.z; acc[15] += xv.w*wv.w;
        }
    }

    // write h tile (coalesced STG.128)
#pragma unroll
    for (int ri = 0; ri < 4; ++ri) {
        float4 o = make_float4(acc[ri*4], acc[ri*4+1], acc[ri*4+2], acc[ri*4+3]);
        *reinterpret_cast<float4*>(
            &g_h[(size_t)(row0 + 4*ty + ri)*Hv + c0 + 4*tx]) = o;
    }

    // partial scores: s1[row] += sum_c acc*a1[c]
    float4 a1 = *reinterpret_cast<const float4*>(&a[c0 + 4*tx]);
    float4 a2 = *reinterpret_cast<const float4*>(&a[Hv + c0 + 4*tx]);
#pragma unroll
    for (int ri = 0; ri < 4; ++ri) {
        float p1 = acc[ri*4]*a1.x + acc[ri*4+1]*a1.y
                 + acc[ri*4+2]*a1.z + acc[ri*4+3]*a1.w;
        float p2 = acc[ri*4]*a2.x + acc[ri*4+1]*a2.y
                 + acc[ri*4+2]*a2.z + acc[ri*4+3]*a2.w;
#pragma unroll
        for (int off = 8; off > 0; off >>= 1) {
            p1 += __shfl_xor_sync(0xffffffffu, p1, off);
            p2 += __shfl_xor_sync(0xffffffffu, p2, off);
        }
        if (tx == 0) {
            atomicAdd(&s1[row0 + 4*ty + ri], p1);
            atomicAdd(&s2[row0 + 4*ty + ri], p2);
        }
    }
}

// ---------------------------------------------------------------------------
// K3: softmax attention + aggregation (+ fused mean on last layer)
// Block: 64 att-rows x 64 channels; 256 threads; thread = 4x4 tile.
// ---------------------------------------------------------------------------
__global__ void k_gat_agg(const int* __restrict__ adj, int layer, int last)
{
    const int b  = blockIdx.z;
    const int i0 = blockIdx.x * 64;
    const int c0 = blockIdx.y * 64;
    const int t  = threadIdx.x;
    const int tx = t & 15, ty = t >> 4;
    const int lane = t & 31, warp = t >> 5;

    const float* s1 = g_zbuf + layer*2*BN;
    const float* s2 = s1 + BN;

    __shared__ float s2_sh[Nv];
    __shared__ __align__(16) float att[Nv * 68];   // [j][i_local]; reused as st
    __shared__ __align__(16) float sh[32 * 64];    // h chunk [j][c]

    if (t < Nv) s2_sh[t] = s2[b*Nv + t];
    __syncthreads();

    // softmax: 8 rows per warp
#pragma unroll
    for (int rr = 0; rr < 8; ++rr) {
        int il = warp*8 + rr;
        int i  = i0 + il;
        float s1i = s1[b*Nv + i];
        const int* adj_row = adj + (size_t)(b*Nv + i)*Nv;
        float e[4];
        float mx = NEG_INF;
#pragma unroll
        for (int q = 0; q < 4; ++q) {
            int jj = lane + q*32;
            float v = s1i + s2_sh[jj];
            v = (v > 0.f) ? v : ALPHA * v;
            v = (adj_row[jj] > 0) ? v : NEG_INF;
            e[q] = v;
            mx = fmaxf(mx, v);
        }
#pragma unroll
        for (int off = 16; off > 0; off >>= 1)
            mx = fmaxf(mx, __shfl_xor_sync(0xffffffffu, mx, off));
        float sum = 0.f;
#pragma unroll
        for (int q = 0; q < 4; ++q) { e[q] = __expf(e[q] - mx); sum += e[q]; }
#pragma unroll
        for (int off = 16; off > 0; off >>= 1)
            sum += __shfl_xor_sync(0xffffffffu, sum, off);
        float inv = 1.f / sum;
#pragma unroll
        for (int q = 0; q < 4; ++q)
            att[(lane + q*32)*68 + il] = e[q] * inv;
    }

    float acc[16];
#pragma unroll
    for (int i = 0; i < 16; ++i) acc[i] = 0.f;

    const float* hb = g_h + (size_t)b*Nv*Hv;

    for (int jc = 0; jc < Nv; jc += 32) {
        __syncthreads();
#pragma unroll
        for (int m = 0; m < 2; ++m) {
            int j = (t >> 4) + 16*m;
            float4 hv = *reinterpret_cast<const float4*>(
                            &hb[(size_t)(jc + j)*Hv + c0 + 4*(t & 15)]);
            *reinterpret_cast<float4*>(&sh[(j<<6) + 4*(t & 15)]) = hv;
        }
        __syncthreads();

#pragma unroll 8
        for (int jj = 0; jj < 32; ++jj) {
            float4 av = *reinterpret_cast<const float4*>(&att[(jc+jj)*68 + 4*ty]);
            float4 hv = *reinterpret_cast<const float4*>(&sh[(jj<<6) + 4*tx]);
            acc[0]  += av.x*hv.x; acc[1]  += av.x*hv.y;
            acc[2]  += av.x*hv.z; acc[3]  += av.x*hv.w;
            acc[4]  += av.y*hv.x; acc[5]  += av.y*hv.y;
            acc[6]  += av.y*hv.z; acc[7]  += av.y*hv.w;
            acc[8]  += av.z*hv.x; acc[9]  += av.z*hv.y;
            acc[10] += av.z*hv.z; acc[11] += av.z*hv.w;
            acc[12] += av.w*hv.x; acc[13] += av.w*hv.y;
            acc[14] += av.w*hv.z; acc[15] += av.w*hv.w;
        }
    }

    if (last) {
        float* graph = g_zbuf + GRAPH_OFF;
#pragma unroll
        for (int ci = 0; ci < 4; ++ci) {
            float p = 0.f;
#pragma unroll
            for (int ri = 0; ri < 4; ++ri)
                p += fmaxf(acc[ri*4 + ci], 0.f);
            atomicAdd(&graph[b*Hv + c0 + 4*tx + ci], p);
        }
    } else {
        // transpose relu(acc) through smem (reuse att as st[i][c], stride 65)
        __syncthreads();
#pragma unroll
        for (int ri = 0; ri < 4; ++ri)
#pragma unroll
            for (int ci = 0; ci < 4; ++ci)
                att[(4*ty + ri)*65 + 4*tx + ci] = fmaxf(acc[ri*4 + ci], 0.f);
        __syncthreads();
        int i  = t & 63;
        int cb = t >> 6;         // 0..3
#pragma unroll
        for (int p = 0; p < 16; ++p) {
            int c = cb + 4*p;
            g_xT[(size_t)(c0 + c)*BN + b*Nv + i0 + i] = att[i*65 + c];
        }
    }
}

// ---------------------------------------------------------------------------
// K5: fused head. One block per batch element.
// ---------------------------------------------------------------------------
__global__ void k_head(const float* __restrict__ scaffold,  // [B,20]
                       const float* __restrict__ W_sc,      // [20,256]
                       const float* __restrict__ b_sc,      // [256]
                       const float* __restrict__ gp_w1,     // [256,128]
                       const float* __restrict__ gp_b1,     // [128]
                       const float* __restrict__ gp_w2,     // [128,64]
                       const float* __restrict__ gp_b2,     // [64]
                       const float* __restrict__ out_w1,    // [128,128]
                       const float* __restrict__ out_b1,    // [128]
                       const float* __restrict__ out_w2,    // [128,13]
                       const float* __restrict__ out_b2,    // [13]
                       float* __restrict__ out)             // [B,13]
{
    int b = blockIdx.x, t = threadIdx.x;
    const float* graph = g_zbuf + GRAPH_OFF;
    __shared__ float scaf[Sv];
    __shared__ float grow[Hv];
    __shared__ float sc[Hv];
    __shared__ float g1[128], sp1[128];
    __shared__ float c[128];
    __shared__ float hdn[128];

    if (t < Sv) scaf[t] = scaffold[b*Sv + t];
    grow[t] = graph[b*Hv + t] * (1.0f/Nv);
    __syncthreads();

    {
        float acc = b_sc[t];
#pragma unroll
        for (int k = 0; k < Sv; ++k)
            acc += scaf[k] * W_sc[k*Hv + t];
        sc[t] = acc;
    }
    __syncthreads();

    {
        int col = t & 127;
        const float* src = (t < 128) ? grow : sc;
        float acc = gp_b1[col];
#pragma unroll 4
        for (int k = 0; k < Hv; ++k)
            acc += src[k] * gp_w1[k*128 + col];
        acc = fmaxf(acc, 0.f);
        if (t < 128) g1[col] = acc; else sp1[col] = acc;
    }
    __syncthreads();

    if (t < 128) {
        int col = t & 63;
        const float* src = (t < 64) ? g1 : sp1;
        float acc = gp_b2[col];
#pragma unroll 4
        for (int k = 0; k < 128; ++k)
            acc += src[k] * gp_w2[k*64 + col];
        c[t] = fmaxf(acc, 0.f);
    }
    __syncthreads();

    if (t < 128) {
        float acc = out_b1[t];
#pragma unroll 4
        for (int k = 0; k < 128; ++k)
            acc += c[k] * out_w1[k*128 + t];
        hdn[t] = fmaxf(acc, 0.f);
    }
    __syncthreads();

    if (t < Tv) {
        float acc = out_b2[t];
#pragma unroll 4
        for (int k = 0; k < 128; ++k)
            acc += hdn[k] * out_w2[k*Tv + t];
        out[b*Tv + t] = acc;
    }
}

// ---------------------------------------------------------------------------
extern "C" void kernel_launch(void* const* d_in, const int* in_sizes, int n_in,
                              void* d_out, int out_size)
{
    const float* node_features     = (const float*)d_in[0];
    // d_in[1] = edge_features — unused by the reference
    const int*   adj_matrix        = (const int*)  d_in[2];
    const float* scaffold_features = (const float*)d_in[3];
    const float* W_node            = (const float*)d_in[4];
    const float* b_node            = (const float*)d_in[5];
    const float* gat_W             = (const float*)d_in[6];
    const float* gat_a             = (const float*)d_in[7];
    const float* W_sc              = (const float*)d_in[8];
    const float* b_sc              = (const float*)d_in[9];
    const float* gp_w1             = (const float*)d_in[10];
    const float* gp_b1             = (const float*)d_in[11];
    const float* gp_w2             = (const float*)d_in[12];
    const float* gp_b2             = (const float*)d_in[13];
    const float* out_w1            = (const float*)d_in[14];
    const float* out_b1            = (const float*)d_in[15];
    const float* out_w2            = (const float*)d_in[16];
    const float* out_b2            = (const float*)d_in[17];
    float* out = (float*)d_out;

    // zero score buffers + graph accumulator (one memset)
    void* zp = nullptr;
    cudaGetSymbolAddress(&zp, g_zbuf);
    cudaMemsetAsync(zp, 0, (Lv*2*BN + Bv*Hv)*sizeof(float));

    k_node_proj<<<BN/NP_ROWS, 256>>>(node_features, W_node, b_node);

    for (int l = 0; l < Lv; ++l) {
        dim3 pg(BN/64, Hv/64);
        k_gat_proj<<<pg, 256>>>(gat_W + (size_t)l*Hv*Hv,
                                gat_a + (size_t)l*2*Hv, l);
        dim3 ag(Nv/64, Hv/64, Bv);
        k_gat_agg<<<ag, 256>>>(adj_matrix, l, l == Lv-1);
    }

    k_head<<<Bv, 256>>>(scaffold_features, W_sc, b_sc,
                        gp_w1, gp_b1, gp_w2, gp_b2,
                        out_w1, out_b1, out_w2, out_b2, out);
}

// round 4
// speedup vs baseline: 1.3219x; 1.0337x over previous
#include <cuda_runtime.h>
#include <cuda_bf16.h>

// Problem constants
#define Bv   32
#define Nv   128
#define Fv   78
#define Hv   256
#define Sv   20
#define Tv   13
#define Lv   3
#define ALPHA 0.2f
#define NEG_INF -9000000000000000.0f

#define BN (Bv*Nv)          // 4096 rows

// Scratch (device globals; no allocation allowed)
__device__ float g_xT[Hv*BN];                 // activations TRANSPOSED [c][row]
__device__ float g_h[BN*Hv];                  // projected h, normal [row][c]
__device__ float g_zbuf[Lv*2*BN + Bv*Hv];     // s1/s2 per layer + graph accum

#define GRAPH_OFF (Lv*2*BN)

// ---------------------------------------------------------------------------
// K1: x = node_features @ W_node + b_node -> g_xT (transposed)
// ---------------------------------------------------------------------------
#define NP_ROWS 8
__global__ void k_node_proj(const float* __restrict__ nf,
                            const float* __restrict__ W,
                            const float* __restrict__ bias)
{
    int row0 = blockIdx.x * NP_ROWS;
    int j    = threadIdx.x;

    __shared__ __align__(16) float sf[Fv * NP_ROWS];   // [f][r]
    __shared__ float st[NP_ROWS * 257];                // transpose tile

    for (int idx = j; idx < Fv*NP_ROWS; idx += 256) {
        int f = idx >> 3, r = idx & 7;
        sf[idx] = nf[(row0 + r)*Fv + f];
    }
    __syncthreads();

    float bj = bias[j];
    float acc[NP_ROWS];
#pragma unroll
    for (int r = 0; r < NP_ROWS; ++r) acc[r] = bj;

#pragma unroll 6
    for (int f = 0; f < Fv; ++f) {
        float w = W[f*Hv + j];
        const float4* xp = reinterpret_cast<const float4*>(&sf[f*NP_ROWS]);
        float4 xa = xp[0], xb = xp[1];
        acc[0] += xa.x * w;  acc[1] += xa.y * w;
        acc[2] += xa.z * w;  acc[3] += xa.w * w;
        acc[4] += xb.x * w;  acc[5] += xb.y * w;
        acc[6] += xb.z * w;  acc[7] += xb.w * w;
    }

#pragma unroll
    for (int r = 0; r < NP_ROWS; ++r)
        st[r*257 + j] = acc[r];
    __syncthreads();
    int r  = j & 7;
    int cb = j >> 3;          // 0..31
#pragma unroll
    for (int p = 0; p < 8; ++p) {
        int c = cb + 32*p;
        g_xT[(size_t)c*BN + row0 + r] = st[r*257 + c];
    }
}

// ---------------------------------------------------------------------------
// K2: h = x @ gat_W[l] + partial scores.
// Block: 32 rows x 64 cols, 128 threads, 4x4/thread, KC=32, double-buffered.
// ---------------------------------------------------------------------------
#define KC 32
#define SXS 36
__global__ void k_gat_proj(const float* __restrict__ W,   // [256,256]
                           const float* __restrict__ a,   // [512]
                           int layer)
{
    const int row0 = blockIdx.x * 32;
    const int c0   = blockIdx.y * 64;
    const int t  = threadIdx.x;
    const int tx = t & 15, ty = t >> 4;        // ty 0..7

    float* s1 = g_zbuf + layer*2*BN;
    float* s2 = s1 + BN;

    __shared__ __align__(16) float sx[2][KC*SXS];   // [k][row]
    __shared__ __align__(16) float sw[2][KC*64];    // [k][col]

    // staging thread mapping
    const int kx = t >> 3, fx = t & 7;     // sx: k=kx+16m (m<2), float4 col fx
    const int kw = t >> 4, fw = t & 15;    // sw: k=kw+8m  (m<4)

    float4 rx[2], rw[4];
    const float* xT = g_xT;

#define LOAD_CHUNK(kc)                                                        \
    {                                                                         \
        _Pragma("unroll")                                                     \
        for (int m = 0; m < 2; ++m)                                           \
            rx[m] = *reinterpret_cast<const float4*>(                         \
                &xT[(size_t)((kc) + kx + 16*m)*BN + row0 + 4*fx]);            \
        _Pragma("unroll")                                                     \
        for (int m = 0; m < 4; ++m)                                           \
            rw[m] = *reinterpret_cast<const float4*>(                         \
                &W[((kc) + kw + 8*m)*Hv + c0 + 4*fw]);                        \
    }
#define STORE_CHUNK(buf)                                                      \
    {                                                                         \
        _Pragma("unroll")                                                     \
        for (int m = 0; m < 2; ++m)                                           \
            *reinterpret_cast<float4*>(&sx[buf][(kx + 16*m)*SXS + 4*fx]) = rx[m]; \
        _Pragma("unroll")                                                     \
        for (int m = 0; m < 4; ++m)                                           \
            *reinterpret_cast<float4*>(&sw[buf][((kw + 8*m)<<6) + 4*fw]) = rw[m]; \
    }

    float acc[16];
#pragma unroll
    for (int i = 0; i < 16; ++i) acc[i] = 0.f;

    LOAD_CHUNK(0);
    STORE_CHUNK(0);
    __syncthreads();

    const int NCH = Hv / KC;      // 8
#pragma unroll
    for (int c = 0; c < NCH; ++c) {
        int cur = c & 1;
        if (c + 1 < NCH) LOAD_CHUNK((c+1)*KC);     // prefetch (latency hidden)

#pragma unroll 8
        for (int k = 0; k < KC; ++k) {
            float4 xv = *reinterpret_cast<const float4*>(&sx[cur][k*SXS + 4*ty]);
            float4 wv = *reinterpret_cast<const float4*>(&sw[cur][(k<<6) + 4*tx]);
            acc[0]  += xv.x*wv.x; acc[1]  += xv.x*wv.y;
            acc[2]  += xv.x*wv.z; acc[3]  += xv.x*wv.w;
            acc[4]  += xv.y*wv.x; acc[5]  += xv.y*wv.y;
            acc[6]  += xv.y*wv.z; acc[7]  += xv.y*wv.w;
            acc[8]  += xv.z*wv.x; acc[9]  += xv.z*wv.y;
            acc[10] += xv.z*wv.z; acc[11] += xv.z*wv.w;
            acc[12] += xv.w*wv.x; acc[13] += xv.w*wv.y;
            acc[14] += xv.w*wv.z; acc[15] += xv.w*wv.w;
        }
        if (c + 1 < NCH) {
            __syncthreads();
            STORE_CHUNK((c+1) & 1);
            __syncthreads();
        }
    }

    // write h tile (coalesced STG.128)
#pragma unroll
    for (int ri = 0; ri < 4; ++ri) {
        float4 o = make_float4(acc[ri*4], acc[ri*4+1], acc[ri*4+2], acc[ri*4+3]);
        *reinterpret_cast<float4*>(
            &g_h[(size_t)(row0 + 4*ty + ri)*Hv + c0 + 4*tx]) = o;
    }

    // partial scores
    float4 a1 = *reinterpret_cast<const float4*>(&a[c0 + 4*tx]);
    float4 a2 = *reinterpret_cast<const float4*>(&a[Hv + c0 + 4*tx]);
#pragma unroll
    for (int ri = 0; ri < 4; ++ri) {
        float p1 = acc[ri*4]*a1.x + acc[ri*4+1]*a1.y
                 + acc[ri*4+2]*a1.z + acc[ri*4+3]*a1.w;
        float p2 = acc[ri*4]*a2.x + acc[ri*4+1]*a2.y
                 + acc[ri*4+2]*a2.z + acc[ri*4+3]*a2.w;
#pragma unroll
        for (int off = 8; off > 0; off >>= 1) {
            p1 += __shfl_xor_sync(0xffffffffu, p1, off);
            p2 += __shfl_xor_sync(0xffffffffu, p2, off);
        }
        if (tx == 0) {
            atomicAdd(&s1[row0 + 4*ty + ri], p1);
            atomicAdd(&s2[row0 + 4*ty + ri], p2);
        }
    }
#undef LOAD_CHUNK
#undef STORE_CHUNK
}

// ---------------------------------------------------------------------------
// K3: softmax attention + aggregation (+ fused mean on last layer)
// Block: 32 att-rows x 64 ch, 128 threads, 4x4/thread, double-buffered h.
// ---------------------------------------------------------------------------
#define JC 32
__global__ void k_gat_agg(const int* __restrict__ adj, int layer, int last)
{
    const int b  = blockIdx.z;
    const int i0 = blockIdx.x * 32;
    const int c0 = blockIdx.y * 64;
    const int t  = threadIdx.x;
    const int tx = t & 15, ty = t >> 4;
    const int lane = t & 31, warp = t >> 5;

    const float* s1 = g_zbuf + layer*2*BN;
    const float* s2 = s1 + BN;

    __shared__ float s2_sh[Nv];
    __shared__ __align__(16) float att[Nv * 36];     // [j][i_local], reused as st
    __shared__ __align__(16) float sh[2][JC * 64];   // h chunks [j][c]

    s2_sh[t] = s2[b*Nv + t];
    __syncthreads();

    // softmax: 8 rows per warp (4 warps x 8 = 32 rows)
#pragma unroll
    for (int rr = 0; rr < 8; ++rr) {
        int il = warp*8 + rr;
        int i  = i0 + il;
        float s1i = s1[b*Nv + i];
        const int* adj_row = adj + (size_t)(b*Nv + i)*Nv;
        float e[4];
        float mx = NEG_INF;
#pragma unroll
        for (int q = 0; q < 4; ++q) {
            int jj = lane + q*32;
            float v = s1i + s2_sh[jj];
            v = (v > 0.f) ? v : ALPHA * v;
            v = (adj_row[jj] > 0) ? v : NEG_INF;
            e[q] = v;
            mx = fmaxf(mx, v);
        }
#pragma unroll
        for (int off = 16; off > 0; off >>= 1)
            mx = fmaxf(mx, __shfl_xor_sync(0xffffffffu, mx, off));
        float sum = 0.f;
#pragma unroll
        for (int q = 0; q < 4; ++q) { e[q] = __expf(e[q] - mx); sum += e[q]; }
#pragma unroll
        for (int off = 16; off > 0; off >>= 1)
            sum += __shfl_xor_sync(0xffffffffu, sum, off);
        float inv = 1.f / sum;
#pragma unroll
        for (int q = 0; q < 4; ++q)
            att[(lane + q*32)*36 + il] = e[q] * inv;
    }

    const float* hb = g_h + (size_t)b*Nv*Hv;
    const int jw = t >> 4, fw = t & 15;    // staging: j = jw + 8m (m<4)
    float4 rh[4];

#define LOAD_H(jc)                                                            \
    {                                                                         \
        _Pragma("unroll")                                                     \
        for (int m = 0; m < 4; ++m)                                           \
            rh[m] = *reinterpret_cast<const float4*>(                         \
                &hb[(size_t)((jc) + jw + 8*m)*Hv + c0 + 4*fw]);               \
    }
#define STORE_H(buf)                                                          \
    {                                                                         \
        _Pragma("unroll")                                                     \
        for (int m = 0; m < 4; ++m)                                           \
            *reinterpret_cast<float4*>(&sh[buf][((jw + 8*m)<<6) + 4*fw]) = rh[m]; \
    }

    float acc[16];
#pragma unroll
    for (int i = 0; i < 16; ++i) acc[i] = 0.f;

    LOAD_H(0);
    STORE_H(0);
    __syncthreads();

    const int NJC = Nv / JC;     // 4
#pragma unroll
    for (int c = 0; c < NJC; ++c) {
        int cur = c & 1;
        if (c + 1 < NJC) LOAD_H((c+1)*JC);

#pragma unroll 8
        for (int jj = 0; jj < JC; ++jj) {
            float4 av = *reinterpret_cast<const float4*>(&att[(c*JC+jj)*36 + 4*ty]);
            float4 hv = *reinterpret_cast<const float4*>(&sh[cur][(jj<<6) + 4*tx]);
            acc[0]  += av.x*hv.x; acc[1]  += av.x*hv.y;
            acc[2]  += av.x*hv.z; acc[3]  += av.x*hv.w;
            acc[4]  += av.y*hv.x; acc[5]  += av.y*hv.y;
            acc[6]  += av.y*hv.z; acc[7]  += av.y*hv.w;
            acc[8]  += av.z*hv.x; acc[9]  += av.z*hv.y;
            acc[10] += av.z*hv.z; acc[11] += av.z*hv.w;
            acc[12] += av.w*hv.x; acc[13] += av.w*hv.y;
            acc[14] += av.w*hv.z; acc[15] += av.w*hv.w;
        }
        if (c + 1 < NJC) {
            __syncthreads();
            STORE_H((c+1) & 1);
            __syncthreads();
        }
    }

    if (last) {
        float* graph = g_zbuf + GRAPH_OFF;
#pragma unroll
        for (int ci = 0; ci < 4; ++ci) {
            float p = 0.f;
#pragma unroll
            for (int ri = 0; ri < 4; ++ri)
                p += fmaxf(acc[ri*4 + ci], 0.f);
            atomicAdd(&graph[b*Hv + c0 + 4*tx + ci], p);
        }
    } else {
        // transpose relu(acc) through smem (reuse att: st[i][c], stride 65)
        __syncthreads();
#pragma unroll
        for (int ri = 0; ri < 4; ++ri)
#pragma unroll
            for (int ci = 0; ci < 4; ++ci)
                att[(4*ty + ri)*65 + 4*tx + ci] = fmaxf(acc[ri*4 + ci], 0.f);
        __syncthreads();
        int i  = t & 31;
        int cb = t >> 5;         // 0..3
#pragma unroll
        for (int p = 0; p < 16; ++p) {
            int c = cb + 4*p;
            g_xT[(size_t)(c0 + c)*BN + b*Nv + i0 + i] = att[i*65 + c];
        }
    }
#undef LOAD_H
#undef STORE_H
}

// ---------------------------------------------------------------------------
// K5: fused head. One block per batch element.
// ---------------------------------------------------------------------------
__global__ void k_head(const float* __restrict__ scaffold,
                       const float* __restrict__ W_sc,
                       const float* __restrict__ b_sc,
                       const float* __restrict__ gp_w1,
                       const float* __restrict__ gp_b1,
                       const float* __restrict__ gp_w2,
                       const float* __restrict__ gp_b2,
                       const float* __restrict__ out_w1,
                       const float* __restrict__ out_b1,
                       const float* __restrict__ out_w2,
                       const float* __restrict__ out_b2,
                       float* __restrict__ out)
{
    int b = blockIdx.x, t = threadIdx.x;
    const float* graph = g_zbuf + GRAPH_OFF;
    __shared__ float scaf[Sv];
    __shared__ float grow[Hv];
    __shared__ float sc[Hv];
    __shared__ float g1[128], sp1[128];
    __shared__ float c[128];
    __shared__ float hdn[128];

    if (t < Sv) scaf[t] = scaffold[b*Sv + t];
    grow[t] = graph[b*Hv + t] * (1.0f/Nv);
    __syncthreads();

    {
        float acc = b_sc[t];
#pragma unroll
        for (int k = 0; k < Sv; ++k)
            acc += scaf[k] * W_sc[k*Hv + t];
        sc[t] = acc;
    }
    __syncthreads();

    {
        int col = t & 127;
        const float* src = (t < 128) ? grow : sc;
        float acc = gp_b1[col];
#pragma unroll 4
        for (int k = 0; k < Hv; ++k)
            acc += src[k] * gp_w1[k*128 + col];
        acc = fmaxf(acc, 0.f);
        if (t < 128) g1[col] = acc; else sp1[col] = acc;
    }
    __syncthreads();

    if (t < 128) {
        int col = t & 63;
        const float* src = (t < 64) ? g1 : sp1;
        float acc = gp_b2[col];
#pragma unroll 4
        for (int k = 0; k < 128; ++k)
            acc += src[k] * gp_w2[k*64 + col];
        c[t] = fmaxf(acc, 0.f);
    }
    __syncthreads();

    if (t < 128) {
        float acc = out_b1[t];
#pragma unroll 4
        for (int k = 0; k < 128; ++k)
            acc += c[k] * out_w1[k*128 + t];
        hdn[t] = fmaxf(acc, 0.f);
    }
    __syncthreads();

    if (t < Tv) {
        float acc = out_b2[t];
#pragma unroll 4
        for (int k = 0; k < 128; ++k)
            acc += hdn[k] * out_w2[k*Tv + t];
        out[b*Tv + t] = acc;
    }
}

// ---------------------------------------------------------------------------
extern "C" void kernel_launch(void* const* d_in, const int* in_sizes, int n_in,
                              void* d_out, int out_size)
{
    const float* node_features     = (const float*)d_in[0];
    // d_in[1] = edge_features — unused by the reference
    const int*   adj_matrix        = (const int*)  d_in[2];
    const float* scaffold_features = (const float*)d_in[3];
    const float* W_node            = (const float*)d_in[4];
    const float* b_node            = (const float*)d_in[5];
    const float* gat_W             = (const float*)d_in[6];
    const float* gat_a             = (const float*)d_in[7];
    const float* W_sc              = (const float*)d_in[8];
    const float* b_sc              = (const float*)d_in[9];
    const float* gp_w1             = (const float*)d_in[10];
    const float* gp_b1             = (const float*)d_in[11];
    const float* gp_w2             = (const float*)d_in[12];
    const float* gp_b2             = (const float*)d_in[13];
    const float* out_w1            = (const float*)d_in[14];
    const float* out_b1            = (const float*)d_in[15];
    const float* out_w2            = (const float*)d_in[16];
    const float* out_b2            = (const float*)d_in[17];
    float* out = (float*)d_out;

    void* zp = nullptr;
    cudaGetSymbolAddress(&zp, g_zbuf);
    cudaMemsetAsync(zp, 0, (Lv*2*BN + Bv*Hv)*sizeof(float));

    k_node_proj<<<BN/NP_ROWS, 256>>>(node_features, W_node, b_node);

    for (int l = 0; l < Lv; ++l) {
        dim3 pg(BN/32, Hv/64);                 // 128 x 4 = 512 blocks
        k_gat_proj<<<pg, 128>>>(gat_W + (size_t)l*Hv*Hv,
                                gat_a + (size_t)l*2*Hv, l);
        dim3 ag(Nv/32, Hv/64, Bv);             // 4 x 4 x 32 = 512 blocks
        k_gat_agg<<<ag, 128>>>(adj_matrix, l, l == Lv-1);
    }

    k_head<<<Bv, 256>>>(scaffold_features, W_sc, b_sc,
                        gp_w1, gp_b1, gp_w2, gp_b2,
                        out_w1, out_b1, out_w2, out_b2, out);
}